// round 4
// baseline (speedup 1.0000x reference)
#include <cuda_runtime.h>

#define Bq  256
#define Tq  2000
#define Fq  80
#define Hq  64
#define G3q 192
#define Oq  29

// Precomputed layer-0 input projection: gx0[b][t][g] (393 MB static device scratch)
__device__ float g_gx0[(size_t)Bq * Tq * G3q];

__device__ __forceinline__ float sigf(float x) {
    return __fdividef(1.0f, 1.0f + __expf(-x));
}
__device__ __forceinline__ float tanhfast(float x) {
    // 2 MUFU + few ALU; rel err ~1e-6 — fine vs 1e-3 gate
    return __fdividef(2.0f, 1.0f + __expf(-2.0f * x)) - 1.0f;
}

// Blackwell packed f32x2 FMA (PTX-only; ptxas never auto-fuses)
__device__ __forceinline__ float2 ffma2(float2 a, float2 b, float2 c) {
    float2 d;
    asm("fma.rn.f32x2 %0, %1, %2, %3;"
        : "=l"(*reinterpret_cast<unsigned long long*>(&d))
        : "l"(*reinterpret_cast<unsigned long long*>(&a)),
          "l"(*reinterpret_cast<unsigned long long*>(&b)),
          "l"(*reinterpret_cast<unsigned long long*>(&c)));
    return d;
}

// ---------------------------------------------------------------------------
// Kernel 1: gx0 = x @ W_ih0^T + b_ih0   (time-parallel GEMM, t-pair f32x2)
// grid = 256 batches * 4 time-quarters; block = 192 threads (1 thread = 1 gate)
// ---------------------------------------------------------------------------
__global__ __launch_bounds__(192) void gx0_kernel(
    const float* __restrict__ x,
    const float* __restrict__ W_ih0,
    const float* __restrict__ b_ih0)
{
    extern __shared__ float sm[];
    float* Wsh = sm;               // [80][192]  W_ih0 transposed
    float* bsh = Wsh + Fq * G3q;   // [192]
    float* xs  = bsh + G3q;        // [80][20]   x tile transposed

    const int tid    = threadIdx.x;
    const int b      = blockIdx.x >> 2;
    const int t0base = (blockIdx.x & 3) * 500;

    for (int idx = tid; idx < G3q * Fq; idx += 192) {
        int gg = idx / Fq, f = idx % Fq;
        Wsh[f * G3q + gg] = W_ih0[idx];
    }
    if (tid < G3q) bsh[tid] = b_ih0[tid];
    __syncthreads();

    const int g = tid;  // gate index 0..191
    for (int c = 0; c < 25; ++c) {
        int t0 = t0base + c * 20;
        for (int idx = tid; idx < 20 * Fq; idx += 192) {
            int tt = idx / Fq, f = idx % Fq;
            xs[f * 20 + tt] = x[((size_t)b * Tq + t0 + tt) * Fq + f];
        }
        __syncthreads();

        float2 acc[10];  // 10 time-pairs
        float bias = bsh[g];
        #pragma unroll
        for (int i = 0; i < 10; ++i) acc[i] = make_float2(bias, bias);

        #pragma unroll 4
        for (int f = 0; f < Fq; ++f) {
            float w = Wsh[f * G3q + g];
            float2 w2 = make_float2(w, w);
            const float4* xv = reinterpret_cast<const float4*>(&xs[f * 20]);
            #pragma unroll
            for (int q = 0; q < 5; ++q) {
                float4 v = xv[q];
                acc[q * 2 + 0] = ffma2(w2, make_float2(v.x, v.y), acc[q * 2 + 0]);
                acc[q * 2 + 1] = ffma2(w2, make_float2(v.z, v.w), acc[q * 2 + 1]);
            }
        }
        #pragma unroll
        for (int i = 0; i < 10; ++i) {
            g_gx0[((size_t)b * Tq + t0 + 2 * i + 0) * G3q + g] = acc[i].x;
            g_gx0[((size_t)b * Tq + t0 + 2 * i + 1) * G3q + g] = acc[i].y;
        }
        __syncthreads();
    }
}

// ---------------------------------------------------------------------------
// Kernel 2: fused 2-layer GRU + FC, register-resident weights, layer-pipelined,
// pairwise named barriers (no block-wide sync in the loop).
//   warps  0-5  (A): W_hh0 rows -> layer 0, time i
//   warps  6-11 (B): W_ih1 rows -> layer 1, time i-1 (+ h1 update)
//   warps 12-17 (C): W_hh1 rows -> layer 1, time i-1
// Barriers: 1 = A internal (192), 2 = B|C dot exchange (384),
//           3 = A|B h0 handoff (384), 4 = B|C h1 handoff (384).
// ---------------------------------------------------------------------------
__global__ __launch_bounds__(576, 1) void rnn_kernel(
    const float* __restrict__ h_in,
    const float* __restrict__ W_hh0, const float* __restrict__ b_hh0,
    const float* __restrict__ W_ih1, const float* __restrict__ W_hh1,
    const float* __restrict__ b_ih1, const float* __restrict__ b_hh1,
    const float* __restrict__ W_fc,  const float* __restrict__ b_fc,
    float* __restrict__ out, int write_hidden)
{
    __shared__ float h0s[2][2][Hq];   // [parity][batch][64]
    __shared__ float h1s[2][Hq];      // [batch][64]
    __shared__ float smA[2][128];     // layer0: gx+d for r,z rows
    __shared__ float smB[2][128];     // layer1: x-side dots for r,z rows
    __shared__ float smC[2][G3q];     // layer1: h-side dots, all rows

    const int tid = threadIdx.x;
    const int grp = tid / G3q;        // 0=A, 1=B, 2=C
    const int g   = tid - grp * G3q;  // row 0..191
    const int b0  = blockIdx.x * 2;
    const int b1  = b0 + 1;

    // --- load this thread's weight row into registers ---
    const float* Wsrc = (grp == 0) ? W_hh0 : (grp == 1) ? W_ih1 : W_hh1;
    float4 w[16];
    #pragma unroll
    for (int i = 0; i < 16; ++i)
        w[i] = reinterpret_cast<const float4*>(Wsrc)[g * 16 + i];
    const float bias = (grp == 0) ? b_hh0[g] : (grp == 1) ? b_ih1[g] : b_hh1[g];

    // --- init hidden state (parity 0) ---
    if (tid < Hq)            h0s[0][0][tid]       = h_in[b0 * Hq + tid];
    else if (tid < 2 * Hq)   h0s[0][1][tid - 64]  = h_in[b1 * Hq + tid - 64];
    else if (tid < 3 * Hq)   h1s[0][tid - 128]    = h_in[Bq * Hq + b0 * Hq + tid - 128];
    else if (tid < 4 * Hq)   h1s[1][tid - 192]    = h_in[Bq * Hq + b1 * Hq + tid - 192];
    __syncthreads();

    const float* gxp0 = g_gx0 + (size_t)b0 * Tq * G3q + g;
    const float* gxp1 = g_gx0 + (size_t)b1 * Tq * G3q + g;
    float gxA0 = 0.0f, gxA1 = 0.0f;
    if (grp == 0) { gxA0 = gxp0[0]; gxA1 = gxp1[0]; }

    for (int i = 0; i <= Tq; ++i) {
        const int p = i & 1;

        // prefetch next step's input projection (group A; hidden behind full step)
        float nx0 = 0.0f, nx1 = 0.0f;
        if (grp == 0 && i + 1 < Tq) {
            nx0 = __ldg(gxp0 + (size_t)(i + 1) * G3q);
            nx1 = __ldg(gxp1 + (size_t)(i + 1) * G3q);
        }

        // --- dot products (both batches) over register weight row ---
        const float* hv0 = (grp == 2) ? h1s[0] : h0s[p][0];
        const float* hv1 = (grp == 2) ? h1s[1] : h0s[p][1];
        float2 aA0 = make_float2(bias, 0.0f), aB0 = make_float2(0.0f, 0.0f);
        float2 aA1 = make_float2(bias, 0.0f), aB1 = make_float2(0.0f, 0.0f);
        #pragma unroll
        for (int k = 0; k < 16; ++k) {
            float4 wv = w[k];
            float4 u  = reinterpret_cast<const float4*>(hv0)[k];
            float4 v  = reinterpret_cast<const float4*>(hv1)[k];
            aA0 = ffma2(make_float2(wv.x, wv.y), make_float2(u.x, u.y), aA0);
            aB0 = ffma2(make_float2(wv.z, wv.w), make_float2(u.z, u.w), aB0);
            aA1 = ffma2(make_float2(wv.x, wv.y), make_float2(v.x, v.y), aA1);
            aB1 = ffma2(make_float2(wv.z, wv.w), make_float2(v.z, v.w), aB1);
        }
        float d0 = (aA0.x + aA0.y) + (aB0.x + aB0.y);
        float d1 = (aA1.x + aA1.y) + (aB1.x + aB1.y);

        if (grp == 0) {
            // ---- layer 0, time i (active for i < Tq) ----
            if (g < 128) {                 // raw pre-activations (sig deferred)
                smA[0][g] = gxA0 + d0;
                smA[1][g] = gxA1 + d1;
            }
            asm volatile("bar.sync 1, 192;" ::: "memory");
            if (i < Tq && g >= 128) {
                int j = g - 128;
                float r0 = sigf(smA[0][j]), z0 = sigf(smA[0][64 + j]);
                float r1 = sigf(smA[1][j]), z1 = sigf(smA[1][64 + j]);
                float n0 = tanhfast(gxA0 + r0 * d0);
                float n1 = tanhfast(gxA1 + r1 * d1);
                h0s[p ^ 1][0][j] = (1.0f - z0) * n0 + z0 * h0s[p][0][j];
                h0s[p ^ 1][1][j] = (1.0f - z1) * n1 + z1 * h0s[p][1][j];
            }
            gxA0 = nx0; gxA1 = nx1;
            asm volatile("bar.sync 3, 384;" ::: "memory");   // h0 handoff A|B
        } else if (grp == 2) {
            // ---- layer 1 h-side dots ----
            smC[0][g] = d0; smC[1][g] = d1;
            asm volatile("bar.sync 2, 384;" ::: "memory");   // dot exchange B|C
            asm volatile("bar.sync 4, 384;" ::: "memory");   // h1 handoff B|C
        } else {
            // ---- group B: layer 1 x-side dots + full gate update ----
            if (g < 128) { smB[0][g] = d0; smB[1][g] = d1; }
            asm volatile("bar.sync 2, 384;" ::: "memory");   // dot exchange B|C
            if (g >= 128 && i > 0) {
                int j = g - 128;
                float r0 = sigf(smB[0][j] + smC[0][j]);
                float z0 = sigf(smB[0][64 + j] + smC[0][64 + j]);
                float r1 = sigf(smB[1][j] + smC[1][j]);
                float z1 = sigf(smB[1][64 + j] + smC[1][64 + j]);
                float n0 = tanhfast(d0 + r0 * smC[0][g]);
                float n1 = tanhfast(d1 + r1 * smC[1][g]);
                h1s[0][j] = (1.0f - z0) * n0 + z0 * h1s[0][j];
                h1s[1][j] = (1.0f - z1) * n1 + z1 * h1s[1][j];
            }
            asm volatile("bar.sync 3, 384;" ::: "memory");   // h0 handoff A|B
            asm volatile("bar.sync 4, 384;" ::: "memory");   // h1 handoff B|C
        }
    }
    __syncthreads();

    // ---- epilogue ----
    const int pf = Tq & 1;  // parity holding h0^(T)
    if (write_hidden && tid < 2 * Hq) {
        int b = tid >> 6, j = tid & 63;
        out[Bq * Oq + (b0 + b) * Hq + j]           = h0s[pf][b][j];
        out[Bq * Oq + Bq * Hq + (b0 + b) * Hq + j] = h1s[b][j];
    }
    if (tid < 2 * Oq) {
        int b = tid / Oq, o = tid - b * Oq;
        float acc = b_fc[o];
        #pragma unroll
        for (int j = 0; j < Hq; ++j)
            acc = fmaf(fmaxf(h1s[b][j], 0.0f), __ldg(&W_fc[o * Hq + j]), acc);
        out[(b0 + b) * Oq + o] = acc;
    }
}

// ---------------------------------------------------------------------------
extern "C" void kernel_launch(void* const* d_in, const int* in_sizes, int n_in,
                              void* d_out, int out_size) {
    const float* x     = (const float*)d_in[0];
    const float* h     = (const float*)d_in[1];
    const float* W_ih0 = (const float*)d_in[2];
    const float* W_hh0 = (const float*)d_in[3];
    const float* b_ih0 = (const float*)d_in[4];
    const float* b_hh0 = (const float*)d_in[5];
    const float* W_ih1 = (const float*)d_in[6];
    const float* W_hh1 = (const float*)d_in[7];
    const float* b_ih1 = (const float*)d_in[8];
    const float* b_hh1 = (const float*)d_in[9];
    const float* W_fc  = (const float*)d_in[10];
    const float* b_fc  = (const float*)d_in[11];
    float* out = (float*)d_out;

    const int smem1 = (Fq * G3q + G3q + Fq * 20) * (int)sizeof(float);  // 68,608 B

    cudaFuncSetAttribute(gx0_kernel, cudaFuncAttributeMaxDynamicSharedMemorySize, smem1);

    gx0_kernel<<<Bq * 4, 192, smem1>>>(x, W_ih0, b_ih0);

    int write_hidden = (out_size >= Bq * Oq + 2 * Bq * Hq) ? 1 : 0;
    rnn_kernel<<<Bq / 2, 576>>>(h, W_hh0, b_hh0,
                                W_ih1, W_hh1, b_ih1, b_hh1,
                                W_fc, b_fc, out, write_hidden);
}